// round 3
// baseline (speedup 1.0000x reference)
#include <cuda_runtime.h>
#include <cuda_bf16.h>

#define N_NODES 50000
#define N_EDGES 800000
#define DIM 128

// ---------------- scratch (static __device__ arrays; no allocation) ----------
__device__ int   g_deg[N_NODES];
__device__ float g_dinv[N_NODES];
__device__ int   g_rowptr[N_NODES + 1];
__device__ int   g_cursor[N_NODES];
__device__ int   g_csrsrc[N_EDGES];
__device__ float g_csrw[N_EDGES];
__device__ float g_bufA[(size_t)N_NODES * DIM];  // GEMM outputs
__device__ float g_bufB[(size_t)N_NODES * DIM];  // h1

// ---------------- graph preprocessing ----------------------------------------
__global__ void init_deg_kernel() {
    int i = blockIdx.x * blockDim.x + threadIdx.x;
    if (i < N_NODES) g_deg[i] = 1;  // self-loop
}

// edge_index is int32 (JAX x64-disabled downcasts the declared int64)
__global__ void count_kernel(const int* __restrict__ ei) {
    int e = blockIdx.x * blockDim.x + threadIdx.x;
    if (e < N_EDGES) {
        unsigned d = (unsigned)ei[N_EDGES + e];
        if (d < N_NODES) atomicAdd(&g_deg[d], 1);
    }
}

// single-block exclusive scan over edge counts (deg-1); also fills dinv + cursor
__global__ void scan_kernel() {
    __shared__ int s[1024];
    const int t = threadIdx.x;
    const int CH = (N_NODES + 1023) / 1024;  // 49
    int start = t * CH;
    int end = start + CH; if (end > N_NODES) end = N_NODES;
    int sum = 0;
    for (int i = start; i < end; i++) sum += g_deg[i] - 1;
    s[t] = sum;
    __syncthreads();
    for (int off = 1; off < 1024; off <<= 1) {
        int v = 0;
        if (t >= off) v = s[t - off];
        __syncthreads();
        if (t >= off) s[t] += v;
        __syncthreads();
    }
    int run = (t == 0) ? 0 : s[t - 1];
    for (int i = start; i < end; i++) {
        g_rowptr[i] = run;
        run += g_deg[i] - 1;
        g_cursor[i] = 0;
        g_dinv[i] = rsqrtf((float)g_deg[i]);
    }
    if (t == 1023) g_rowptr[N_NODES] = s[1023];
}

__global__ void scatter_kernel(const int* __restrict__ ei) {
    int e = blockIdx.x * blockDim.x + threadIdx.x;
    if (e < N_EDGES) {
        unsigned src = (unsigned)ei[e];
        unsigned dst = (unsigned)ei[N_EDGES + e];
        if (src < N_NODES && dst < N_NODES) {
            int pos = g_rowptr[dst] + atomicAdd(&g_cursor[dst], 1);
            g_csrsrc[pos] = src;
            g_csrw[pos] = g_dinv[src] * g_dinv[dst];
        }
    }
}

// ---------------- GEMM: C[M,128] = A[M,128] * W[128,128] (+bias) --------------
// 256 threads/block, 64 rows/block, each thread computes 8 rows x 4 cols.
// SRC_BUF: 0 = read from param A, 1 = read from g_bufB
// DST: 0 = write g_bufA, 1 = write param C
template <int SRC_BUF, int DST, bool ADD_BIAS>
__global__ void gemm128_kernel(const float* __restrict__ A,
                               const float* __restrict__ W,
                               const float* __restrict__ bias,
                               float* __restrict__ C, int M) {
    __shared__ float as[64][DIM];
    const int tx = threadIdx.x & 31;   // col group (float4)
    const int ty = threadIdx.x >> 5;   // row group 0..7
    const int row0 = blockIdx.x * 64;

    const float4* A4 = SRC_BUF ? (const float4*)g_bufB : (const float4*)A;
    for (int i = threadIdx.x; i < 64 * 32; i += 256) {
        int r = i >> 5, c = i & 31;
        float4 v = make_float4(0.f, 0.f, 0.f, 0.f);
        if (row0 + r < M) v = A4[(size_t)(row0 + r) * 32 + c];
        ((float4*)as[r])[c] = v;
    }
    __syncthreads();

    float4 acc[8];
#pragma unroll
    for (int r = 0; r < 8; r++) acc[r] = make_float4(0.f, 0.f, 0.f, 0.f);

    const float4* W4 = (const float4*)W;
#pragma unroll 4
    for (int k = 0; k < DIM; k++) {
        float4 w = __ldg(&W4[k * 32 + tx]);
#pragma unroll
        for (int r = 0; r < 8; r++) {
            float a = as[ty * 8 + r][k];
            acc[r].x += a * w.x;
            acc[r].y += a * w.y;
            acc[r].z += a * w.z;
            acc[r].w += a * w.w;
        }
    }

    float4 bv = make_float4(0.f, 0.f, 0.f, 0.f);
    if (ADD_BIAS) bv = ((const float4*)bias)[tx];
    float4* Cout = DST ? (float4*)C : (float4*)g_bufA;
#pragma unroll
    for (int r = 0; r < 8; r++) {
        int row = row0 + ty * 8 + r;
        if (row < M) {
            float4 o = acc[r];
            if (ADD_BIAS) { o.x += bv.x; o.y += bv.y; o.z += bv.z; o.w += bv.w; }
            Cout[(size_t)row * 32 + tx] = o;
        }
    }
}

// ---------------- aggregation: out[i] = sum_j norm*h[src] + self + bias -------
// reads g_bufA; DST_BUF: 1 = write g_bufB, 0 = write param out
// block = (32,4): 32 lanes (float4 over 128 feats) x 4 nodes per block
template <int DST_BUF, bool RELU>
__global__ void aggregate_kernel(const float* __restrict__ bias,
                                 float* __restrict__ out) {
    int node = blockIdx.x * 4 + threadIdx.y;
    if (node >= N_NODES) return;
    int lane = threadIdx.x;

    const float4* H4 = (const float4*)g_bufA;
    float di = g_dinv[node];
    float w0 = di * di;
    float4 h = H4[(size_t)node * 32 + lane];
    float4 acc = make_float4(h.x * w0, h.y * w0, h.z * w0, h.w * w0);

    int beg = g_rowptr[node];
    int end = g_rowptr[node + 1];
    for (int j = beg; j < end; j++) {
        int s = g_csrsrc[j];
        float w = g_csrw[j];
        float4 v = H4[(size_t)s * 32 + lane];
        acc.x += v.x * w;
        acc.y += v.y * w;
        acc.z += v.z * w;
        acc.w += v.w * w;
    }

    float4 bv = ((const float4*)bias)[lane];
    acc.x += bv.x; acc.y += bv.y; acc.z += bv.z; acc.w += bv.w;
    if (RELU) {
        acc.x = fmaxf(acc.x, 0.f);
        acc.y = fmaxf(acc.y, 0.f);
        acc.z = fmaxf(acc.z, 0.f);
        acc.w = fmaxf(acc.w, 0.f);
    }
    float4* O = DST_BUF ? (float4*)g_bufB : (float4*)out;
    O[(size_t)node * 32 + lane] = acc;
}

// ---------------- launch ------------------------------------------------------
extern "C" void kernel_launch(void* const* d_in, const int* in_sizes, int n_in,
                              void* d_out, int out_size) {
    const float* x    = (const float*)d_in[0];
    const int*   ei   = (const int*)d_in[1];
    const float* qemb = (const float*)d_in[2];
    const float* W1   = (const float*)d_in[3];
    const float* b1   = (const float*)d_in[4];
    const float* W2   = (const float*)d_in[5];
    const float* b2   = (const float*)d_in[6];
    const float* Wq   = (const float*)d_in[7];
    const float* bq   = (const float*)d_in[8];

    float* out = (float*)d_out;
    float* out_ques = out;                          // [20000,128]
    float* out_h2   = out + (size_t)20000 * DIM;    // [50000,128]

    // graph preprocessing (CSR build, shared by both layers)
    init_deg_kernel<<<(N_NODES + 255) / 256, 256>>>();
    count_kernel<<<(N_EDGES + 255) / 256, 256>>>(ei);
    scan_kernel<<<1, 1024>>>();
    scatter_kernel<<<(N_EDGES + 255) / 256, 256>>>(ei);

    const int gblk = 256;
    // layer 1: g_bufA = x @ W1 ; g_bufB = relu(agg(g_bufA) + b1)
    gemm128_kernel<0, 0, false><<<(N_NODES + 63) / 64, gblk>>>(x, W1, nullptr, nullptr, N_NODES);
    aggregate_kernel<1, true><<<(N_NODES + 3) / 4, dim3(32, 4)>>>(b1, nullptr);
    // layer 2: g_bufA = g_bufB @ W2 ; out_h2 = agg(g_bufA) + b2
    gemm128_kernel<1, 0, false><<<(N_NODES + 63) / 64, gblk>>>(nullptr, W2, nullptr, nullptr, N_NODES);
    aggregate_kernel<0, false><<<(N_NODES + 3) / 4, dim3(32, 4)>>>(b2, out_h2);
    // question path: ques = q_emb @ Wq + bq
    gemm128_kernel<0, 1, true><<<(20000 + 63) / 64, gblk>>>(qemb, Wq, bq, out_ques, 20000);
}